// round 10
// baseline (speedup 1.0000x reference)
#include <cuda_runtime.h>
#include <math.h>

#define NIMG 48            // B*C = 16*3
#define NBATCH 16
#define N 1024
#define OUT_HW 224
#define W 513              // kept kx columns (Hermitian half)
#define WB 516             // padded kx rows in g_B (4 cols per colfft block)
#define KRAD (1024.0f/224.0f)
#define KSCL (224.0f/1024.0f)

#define SFFT 1056          // 32*33 u64 per-FFT exchange buffer
#define PS(e) ((e) + ((e) >> 5))   // natural index -> padded offset (e + 33*k1 form)

typedef unsigned long long u64;

// scratch (static device arrays; no allocation allowed)
__device__ u64   g_B[(size_t)NIMG * WB * N];        // column-major spectra [img][kx][y]
__device__ float g_T[(size_t)NIMG * N * OUT_HW];    // ky-resized [img][kxs][oy]
__device__ u64   g_twf[N];                          // W_1024^j, full table
__device__ unsigned int g_mn[NBATCH];
__device__ unsigned int g_mx[NBATCH];

// ---------- packed f32x2 complex primitives ----------
__device__ __forceinline__ u64 pk(float x, float y) {
    u64 r; asm("mov.b64 %0, {%1,%2};" : "=l"(r) : "f"(x), "f"(y)); return r;
}
__device__ __forceinline__ void upk(u64 a, float& x, float& y) {
    asm("mov.b64 {%0,%1}, %2;" : "=f"(x), "=f"(y) : "l"(a));
}
__device__ __forceinline__ u64 vadd(u64 a, u64 b) {
    u64 r; asm("add.rn.f32x2 %0, %1, %2;" : "=l"(r) : "l"(a), "l"(b)); return r;
}
__device__ __forceinline__ u64 vfma(u64 a, u64 b, u64 c) {
    u64 r; asm("fma.rn.f32x2 %0, %1, %2, %3;" : "=l"(r) : "l"(a), "l"(b), "l"(c)); return r;
}
#define K_NEG1 0xBF800000BF800000ULL   // (-1,-1)
__device__ __forceinline__ u64 vsub(u64 a, u64 b) { return vfma(b, K_NEG1, a); }  // a-b

__device__ __forceinline__ u64 cmul(u64 a, u64 b) {
    float ax, ay, bx, by; upk(a, ax, ay); upk(b, bx, by);
    return pk(ax*bx - ay*by, ax*by + ay*bx);
}
__device__ __forceinline__ u64 cmulc(u64 a, float bx, float by) {
    float ax, ay; upk(a, ax, ay);
    return pk(ax*bx - ay*by, ax*by + ay*bx);
}

// 5-bit bit reversal (compile-time under unrolled loops)
__device__ __forceinline__ constexpr int br5(int j) {
    return ((j & 1) << 4) | ((j & 2) << 2) | (j & 4) | ((j & 8) >> 2) | ((j & 16) >> 4);
}

// 32-pt radix-2 DIT FFT, fully in registers. Input must be bit-reversed
// (a[j] = sample br5(j)); output natural order. All twiddles literal.
__device__ __forceinline__ void fft32_reg(u64 a[32]) {
    const float WC[16] = {
        1.0f, 0.98078528f, 0.92387953f, 0.83146961f,
        0.70710678f, 0.55557023f, 0.38268343f, 0.19509032f,
        0.0f, -0.19509032f, -0.38268343f, -0.55557023f,
        -0.70710678f, -0.83146961f, -0.92387953f, -0.98078528f };
    const float WS[16] = {
        0.0f, -0.19509032f, -0.38268343f, -0.55557023f,
        -0.70710678f, -0.83146961f, -0.92387953f, -0.98078528f,
        -1.0f, -0.98078528f, -0.92387953f, -0.83146961f,
        -0.70710678f, -0.55557023f, -0.38268343f, -0.19509032f };
    #pragma unroll
    for (int s = 1; s <= 5; ++s) {
        const int m = 1 << s, h = m >> 1;
        #pragma unroll
        for (int k = 0; k < 32; k += m) {
            #pragma unroll
            for (int j = 0; j < h; ++j) {
                const int idx = j << (5 - s);      // exponent for W32 table
                u64 hi = a[k + j + h];
                u64 tt;
                if (idx == 0)       tt = hi;
                else if (idx == 8) { float hx, hy; upk(hi, hx, hy); tt = pk(hy, -hx); }
                else                tt = cmulc(hi, WC[idx], WS[idx]);
                u64 u = a[k + j];
                a[k + j]     = vadd(u, tt);
                a[k + j + h] = vsub(u, tt);
            }
        }
    }
}

// middle twiddle: a[k2] *= W_1024^(t*k2), chain with exact resets every 8
__device__ __forceinline__ void mid_twiddle(u64 a[32], int t) {
    u64 wstep = g_twf[t];
    u64 wcur = wstep;
    a[1] = cmul(a[1], wcur);
    #pragma unroll
    for (int k2 = 2; k2 < 32; ++k2) {
        if ((k2 & 7) == 0) wcur = g_twf[(t * k2) & (N - 1)];
        else               wcur = cmul(wcur, wstep);
        a[k2] = cmul(a[k2], wcur);
    }
}

__global__ void k_init(void) {
    int t = threadIdx.x;
    if (t < NBATCH) { g_mn[t] = 0x7f800000u; g_mx[t] = 0u; }
    for (int j = t; j < N; j += 256) {
        float sn, cs;
        sincosf(-6.283185307179586f * (float)j / (float)N, &sn, &cs);
        g_twf[j] = pk(cs, sn);
    }
}

// 4 FFTs per 128-thread block, one warp per FFT; each FFT = two real rows
// (ya, ya+512) packed complex. One shared exchange; no block barrier until
// the transposed Hermitian unpack.
__global__ void __launch_bounds__(128) k_rowfft(const float* __restrict__ in) {
    __shared__ u64 s4[4][SFFT];
    int T = threadIdx.x, f = T >> 5, t = T & 31;
    int bx  = blockIdx.x;               // img*128 + rg
    int img = bx >> 7;
    int rg  = bx & 127;
    int ya  = 4*rg + f;

    const float* ra = in + ((size_t)img * N + ya) * N;
    const float* rb = ra + (size_t)512 * N;
    u64 a[32];
    #pragma unroll
    for (int j = 0; j < 32; ++j) {
        int gi = t + 32 * br5(j);
        a[j] = pk(ra[gi], rb[gi]);
    }
    fft32_reg(a);                       // y[t][k2], natural k2
    mid_twiddle(a, t);
    u64* s = s4[f];
    #pragma unroll
    for (int k2 = 0; k2 < 32; ++k2) s[t*33 + k2] = a[k2];
    __syncwarp();
    u64 b[32];
    #pragma unroll
    for (int j = 0; j < 32; ++j) b[j] = s[br5(j)*33 + t];
    __syncwarp();                       // all lanes done reading s
    fft32_reg(b);                       // b[k1] = X[t + 32*k1]
    // natural-order store: X[e] -> s[PS(e)], e = t + 32*k1 -> offset t + 33*k1
    #pragma unroll
    for (int k1 = 0; k1 < 32; ++k1) s[33*k1 + t] = b[k1];
    __syncthreads();                    // all 4 FFTs resident

    // transposed Hermitian unpack: keep kx = 0..512, 32B chunks into g_B
    int ybase = 4 * rg;
    for (int e = T; e < W; e += 128) {
        int em = (N - e) & (N - 1);
        u64 va[4], vb[4];
        #pragma unroll
        for (int g = 0; g < 4; ++g) {
            float zx, zy, mxx, mxy;
            upk(s4[g][PS(e)],  zx, zy);
            upk(s4[g][PS(em)], mxx, mxy);
            va[g] = pk(0.5f*(zx + mxx), 0.5f*(zy - mxy));
            vb[g] = pk(0.5f*(zy + mxy), 0.5f*(mxx - zx));
        }
        u64* pa = g_B + ((size_t)img * WB + e) * N + ybase;
        u64* pb = pa + 512;
        *reinterpret_cast<ulonglong2*>(pa)     = make_ulonglong2(va[0], va[1]);
        *reinterpret_cast<ulonglong2*>(pa + 2) = make_ulonglong2(va[2], va[3]);
        *reinterpret_cast<ulonglong2*>(pb)     = make_ulonglong2(vb[0], vb[1]);
        *reinterpret_cast<ulonglong2*>(pb + 2) = make_ulonglong2(vb[2], vb[3]);
    }
}

// One warp per column FFT; 4 columns per 128-thread block. Fully
// warp-autonomous: the exchange buffer is reused as the m[] magnitude array.
__global__ void __launch_bounds__(128) k_colfft(void) {
    __shared__ u64 s4[4][SFFT];
    int T = threadIdx.x, f = T >> 5, t = T & 31;
    int bx  = blockIdx.x;               // img*129 + cg
    int img = bx / 129;
    int cg  = bx - img * 129;
    int kx  = 4*cg + f;                 // 0..515 (513..515 are padding)
    bool valid = (kx < W);

    const u64* cp = g_B + ((size_t)img * WB + kx) * N;
    u64 a[32];
    #pragma unroll
    for (int j = 0; j < 32; ++j)
        a[j] = cp[t + 32 * br5(j)];
    fft32_reg(a);
    mid_twiddle(a, t);
    u64* s = s4[f];
    #pragma unroll
    for (int k2 = 0; k2 < 32; ++k2) s[t*33 + k2] = a[k2];
    __syncwarp();
    u64 b[32];
    #pragma unroll
    for (int j = 0; j < 32; ++j) b[j] = s[br5(j)*33 + t];
    __syncwarp();                       // lanes done reading: s reusable as m
    fft32_reg(b);                       // b[k1] = X[t + 32*k1]

    // log-magnitude from registers; fftshift (+512 = +16 in k1) into m = s
    float* m = reinterpret_cast<float*>(s);
    float mn = 3.4e38f, mx = 0.0f;
    #pragma unroll
    for (int k1 = 0; k1 < 32; ++k1) {
        float vx, vy; upk(b[k1], vx, vy);
        float mag = log1pf(sqrtf(vx*vx + vy*vy));
        m[t + 32*((k1 + 16) & 31)] = mag;
        mn = fminf(mn, mag); mx = fmaxf(mx, mag);
    }
    #pragma unroll
    for (int o = 16; o; o >>= 1) {
        mn = fminf(mn, __shfl_xor_sync(0xffffffffu, mn, o));
        mx = fmaxf(mx, __shfl_xor_sync(0xffffffffu, mx, o));
    }
    if (t == 0 && valid) {
        int bb = img / 3;               // img = batch*3 + channel
        atomicMin(&g_mn[bb], __float_as_uint(mn));
        atomicMax(&g_mx[bb], __float_as_uint(mx));
    }
    __syncwarp();                       // m[] visible to all lanes

    // antialiased triangle resize along kys (ramp weights), column + mirror
    if (valid) {
        int kxs1 = (kx + 512) & (N - 1);
        int kxs2 = 512 - kx;
        float* gt1 = g_T + ((size_t)img * N + kxs1) * OUT_HW;
        float* gt2 = g_T + ((size_t)img * N + kxs2) * OUT_HW;
        for (int oy = t; oy < OUT_HW; oy += 32) {
            float sf = ((float)oy + 0.5f) * (1024.0f/224.0f) - 0.5f;
            int i0 = max(0, (int)ceilf(sf - KRAD));
            int i1 = min(N - 1, (int)floorf(sf + KRAD));
            int ip = (int)floorf(sf);
            float acc1 = 0.0f, acc2 = 0.0f, sw = 0.0f;
            float w = 1.0f - (sf - (float)i0) * KSCL;
            int i = i0;
            for (; i <= ip; ++i) {
                acc1 += w * m[i];
                acc2 += w * m[(N - i) & (N - 1)];
                sw += w; w += KSCL;
            }
            w = 1.0f - ((float)i - sf) * KSCL;
            for (; i <= i1; ++i) {
                acc1 += w * m[i];
                acc2 += w * m[(N - i) & (N - 1)];
                sw += w; w -= KSCL;
            }
            float inv = 1.0f / sw;
            gt1[oy] = acc1 * inv;
            gt2[oy] = acc2 * inv;
        }
    }
}

__global__ void __launch_bounds__(224) k_resize2(float* __restrict__ out) {
    int blk = blockIdx.x;               // img*224 + ox
    int img = blk / OUT_HW;
    int ox  = blk - img * OUT_HW;
    int oy  = threadIdx.x;
    float sf = ((float)ox + 0.5f) * (1024.0f/224.0f) - 0.5f;
    int i0 = max(0, (int)ceilf(sf - KRAD));
    int i1 = min(N - 1, (int)floorf(sf + KRAD));
    int ip = (int)floorf(sf);
    float acc = 0.0f, sw = 0.0f;
    const float* base = g_T + (size_t)img * N * OUT_HW + oy;
    float w = 1.0f - (sf - (float)i0) * KSCL;
    int i = i0;
    for (; i <= ip; ++i) { acc += w * base[(size_t)i * OUT_HW]; sw += w; w += KSCL; }
    w = 1.0f - ((float)i - sf) * KSCL;
    for (; i <= i1; ++i) { acc += w * base[(size_t)i * OUT_HW]; sw += w; w -= KSCL; }
    int b = img / 3;
    float mn = __uint_as_float(g_mn[b]);
    float mx = __uint_as_float(g_mx[b]);
    float v = (acc / sw - mn) / (mx - mn + 1e-8f);
    out[((size_t)img * OUT_HW + oy) * OUT_HW + ox] = v;
}

extern "C" void kernel_launch(void* const* d_in, const int* in_sizes, int n_in,
                              void* d_out, int out_size) {
    (void)in_sizes; (void)n_in; (void)out_size;
    const float* in = (const float*)d_in[0];
    float* out = (float*)d_out;

    k_init<<<1, 256>>>();
    k_rowfft<<<NIMG * 128, 128>>>(in);
    k_colfft<<<NIMG * 129, 128>>>();
    k_resize2<<<NIMG * OUT_HW, 224>>>(out);
}

// round 11
// speedup vs baseline: 2.9913x; 2.9913x over previous
#include <cuda_runtime.h>
#include <math.h>

#define NIMG 48            // B*C = 16*3
#define NBATCH 16
#define N 1024
#define OUT_HW 224
#define W 513              // kept kx columns (Hermitian half)
#define WB 514             // padded kx rows in g_B
#define KRAD (1024.0f/224.0f)
#define KSCL (224.0f/1024.0f)

// padded shared indexing (generic form, used only in the Hermitian unpack)
#define P(i)  ((i) + ((i) >> 4) + ((i) >> 8))
#define S_SZ  1092
#define TW_SZ 272

typedef unsigned long long u64;

// scratch (static device arrays; no allocation allowed)
__device__ u64   g_B[(size_t)NIMG * WB * N];        // column-major spectra [img][kx][y]
__device__ float g_T[(size_t)NIMG * N * OUT_HW];    // ky-resized [img][kxs][oy]
__device__ u64   g_tw[256];
__device__ unsigned int g_mn[NBATCH];
__device__ unsigned int g_mx[NBATCH];

// ---------- packed f32x2 complex primitives ----------
__device__ __forceinline__ u64 pk(float x, float y) {
    u64 r; asm("mov.b64 %0, {%1,%2};" : "=l"(r) : "f"(x), "f"(y)); return r;
}
__device__ __forceinline__ void upk(u64 a, float& x, float& y) {
    asm("mov.b64 {%0,%1}, %2;" : "=f"(x), "=f"(y) : "l"(a));
}
__device__ __forceinline__ u64 vadd(u64 a, u64 b) {
    u64 r; asm("add.rn.f32x2 %0, %1, %2;" : "=l"(r) : "l"(a), "l"(b)); return r;
}
__device__ __forceinline__ u64 vfma(u64 a, u64 b, u64 c) {
    u64 r; asm("fma.rn.f32x2 %0, %1, %2, %3;" : "=l"(r) : "l"(a), "l"(b), "l"(c)); return r;
}
#define K_NEG1 0xBF800000BF800000ULL   // (-1,-1)
#define K_PM1  0xBF8000003F800000ULL   // lo:+1, hi:-1
#define K_MP1  0x3F800000BF800000ULL   // lo:-1, hi:+1
__device__ __forceinline__ u64 vsub(u64 a, u64 b) { return vfma(b, K_NEG1, a); }  // a-b

// scalar complex multiply on packed values
__device__ __forceinline__ u64 cmul(u64 a, u64 b) {
    float ax, ay, bx, by; upk(a, ax, ay); upk(b, bx, by);
    return pk(ax*bx - ay*by, ax*by + ay*bx);
}
__device__ __forceinline__ u64 cmulc(u64 a, float bx, float by) {
    float ax, ay; upk(a, ax, ay);
    return pk(ax*bx - ay*by, ax*by + ay*bx);
}

// packed radix-4 DIT butterfly, in place
__device__ __forceinline__ void bfly4p(u64& x0, u64& x1, u64& x2, u64& x3) {
    u64 u0 = vadd(x0, x2);
    u64 u1 = vsub(x0, x2);
    u64 u2 = vadd(x1, x3);
    u64 u3 = vsub(x1, x3);
    x0 = vadd(u0, u2);
    x2 = vsub(u0, u2);
    float ux, uy; upk(u3, ux, uy);
    u64 sw = pk(uy, ux);
    x1 = vfma(sw, K_PM1, u1);   // (u1.x + u3.y, u1.y - u3.x)
    x3 = vfma(sw, K_MP1, u1);   // (u1.x - u3.y, u1.y + u3.x)
}

// butterfly with precomputed twiddle powers
__device__ __forceinline__ void stage3(u64& a0, u64& a1, u64& a2, u64& a3,
                                       u64 w1, u64 w2, u64 w3) {
    a1 = cmul(a1, w1); a2 = cmul(a2, w2); a3 = cmul(a3, w3);
    bfly4p(a0, a1, a2, a3);
}

// base-4 digit reversal of a 6-bit index (64 = 4^3), self-inverse
__device__ __forceinline__ int rev4_6(int b) {
    return ((b & 3) << 4) | (b & 12) | (b >> 4);
}

// ---------- FFT phases (1024 pts, 64 threads/FFT, 16 pts/thread) ----------
// phase 1: stages 0+1 in registers, store to shared at affine offsets.
// Caller passes b = rev4_6(L) so the global loads stay contiguous in L.
__device__ __forceinline__ void fft_ph1(u64 x[16], u64* s, int b) {
    #pragma unroll
    for (int k = 0; k < 4; ++k) bfly4p(x[4*k], x[4*k+1], x[4*k+2], x[4*k+3]);
    bfly4p(x[0], x[4], x[8], x[12]);                       // pos=0: no twiddle
    x[5]  = cmulc(x[5],   0.92387953f, -0.38268343f);      // pos=1: w, w^2, w^3
    x[9]  = cmulc(x[9],   0.70710678f, -0.70710678f);
    x[13] = cmulc(x[13],  0.38268343f, -0.92387953f);
    bfly4p(x[1], x[5], x[9], x[13]);
    x[6]  = cmulc(x[6],   0.70710678f, -0.70710678f);      // pos=2
    x[10] = cmulc(x[10],  0.0f,        -1.0f);
    x[14] = cmulc(x[14], -0.70710678f, -0.70710678f);
    bfly4p(x[2], x[6], x[10], x[14]);
    x[7]  = cmulc(x[7],   0.38268343f, -0.92387953f);      // pos=3
    x[11] = cmulc(x[11], -0.70710678f, -0.70710678f);
    x[15] = cmulc(x[15], -0.92387953f,  0.38268343f);
    bfly4p(x[3], x[7], x[11], x[15]);
    int b17 = 17*b + (b >> 4);          // == P(16b + j) - j
    #pragma unroll
    for (int j = 0; j < 16; ++j) s[b17 + j] = x[j];
}

// phase 2: stages 2+3 in registers. P(c+16q2+64q3+256hi) = (c+273hi)+17q2+68q3
__device__ __forceinline__ void fft_ph2(u64* s, const u64* tw, int L) {
    int c = L & 15, hi = L >> 4;
    int base = c + 273*hi;
    u64 x[16];
    #pragma unroll
    for (int q3 = 0; q3 < 4; ++q3)
        #pragma unroll
        for (int q2 = 0; q2 < 4; ++q2)
            x[q2 + 4*q3] = s[base + 17*q2 + 68*q3];
    u64 w1 = tw[17*c];                  // PT(16c) = 17c
    u64 w2 = cmul(w1, w1);
    u64 w3 = cmul(w2, w1);
    #pragma unroll
    for (int q3 = 0; q3 < 4; ++q3)
        stage3(x[4*q3], x[4*q3+1], x[4*q3+2], x[4*q3+3], w1, w2, w3);
    u64 v1 = tw[4*c + (c >> 2)];        // PT(4c)
    const float wc[4] = {1.0f, 0.92387953f, 0.70710678f, 0.38268343f};
    const float ws[4] = {0.0f, -0.38268343f, -0.70710678f, -0.92387953f};
    #pragma unroll
    for (int q2 = 0; q2 < 4; ++q2) {
        u64 w = (q2 == 0) ? v1 : cmulc(v1, wc[q2], ws[q2]);
        u64 ww2 = cmul(w, w);
        u64 ww3 = cmul(ww2, w);
        stage3(x[q2], x[q2+4], x[q2+8], x[q2+12], w, ww2, ww3);
    }
    #pragma unroll
    for (int q3 = 0; q3 < 4; ++q3)
        #pragma unroll
        for (int q2 = 0; q2 < 4; ++q2)
            s[base + 17*q2 + 68*q3] = x[q2 + 4*q3];
}

// phase 3: stage 4. P(4L+k+256q) = (4L+(L>>2)) + k + 273q; tw index = base+k.
// Result: x[k+4q] = DFT[4L+k+256q] (natural order).
__device__ __forceinline__ void fft_ph3(u64* s, const u64* tw, int L, u64 x[16]) {
    int base = 4*L + (L >> 2);
    #pragma unroll
    for (int k = 0; k < 4; ++k) {
        u64 w1 = tw[base + k];
        u64 w2 = cmul(w1, w1);
        u64 w3 = cmul(w2, w1);
        u64 a0 = s[base + k];
        u64 a1 = s[base + k + 273];
        u64 a2 = s[base + k + 546];
        u64 a3 = s[base + k + 819];
        a1 = cmul(a1, w1); a2 = cmul(a2, w2); a3 = cmul(a3, w3);
        bfly4p(a0, a1, a2, a3);
        x[k] = a0; x[k+4] = a1; x[k+8] = a2; x[k+12] = a3;
    }
}

__global__ void k_init(void) {
    int t = threadIdx.x;
    if (t < NBATCH) { g_mn[t] = 0x7f800000u; g_mx[t] = 0u; }
    float sn, cs;
    sincosf(-6.283185307179586f * (float)t / 1024.0f, &sn, &cs);
    g_tw[t] = pk(cs, sn);
}

// 4 FFTs per 256-thread block; each FFT = two real rows (ya, ya+512) packed.
// Hermitian unpack writes transposed 32B chunks directly into g_B.
__global__ void __launch_bounds__(256) k_rowfft(const float* __restrict__ in) {
    __shared__ u64 s[4][S_SZ];
    __shared__ u64 tw[TW_SZ];
    int T = threadIdx.x, f = T >> 6, L = T & 63;
    tw[T + (T >> 4)] = g_tw[T];         // PT(T)
    int bx  = blockIdx.x;               // img*128 + rg
    int img = bx >> 7;
    int rg  = bx & 127;
    int ya  = 4*rg + f;
    __syncthreads();                    // tw ready

    const float* ra = in + ((size_t)img * N + ya) * N;
    const float* rb = ra + (size_t)512 * N;
    // relabeled: this thread runs butterfly group rev4_6(L) -> contiguous loads
    u64 x[16];
    #pragma unroll
    for (int j = 0; j < 16; ++j) {
        int gi = L + 64*((j >> 2) & 3) + 256*(j & 3);
        x[j] = pk(ra[gi], rb[gi]);
    }
    fft_ph1(x, s[f], rev4_6(L));
    __syncthreads();
    fft_ph2(s[f], tw, L);
    __syncthreads();
    fft_ph3(s[f], tw, L, x);
    {   // store naturally-ordered results (same addresses ph3 read: no sync needed)
        int base = 4*L + (L >> 2);
        #pragma unroll
        for (int k = 0; k < 4; ++k)
            #pragma unroll
            for (int q = 0; q < 4; ++q)
                s[f][base + k + 273*q] = x[k + 4*q];
    }
    __syncthreads();                    // all 4 FFTs resident

    // transposed Hermitian unpack: keep kx = 0..512
    int ybase = 4 * rg;
    for (int e = T; e < W; e += 256) {
        int em = (N - e) & (N - 1);
        u64 va[4], vb[4];
        #pragma unroll
        for (int g = 0; g < 4; ++g) {
            float zx, zy, mxx, mxy;
            upk(s[g][P(e)],  zx, zy);
            upk(s[g][P(em)], mxx, mxy);
            va[g] = pk(0.5f*(zx + mxx), 0.5f*(zy - mxy));
            vb[g] = pk(0.5f*(zy + mxy), 0.5f*(mxx - zx));
        }
        u64* pa = g_B + ((size_t)img * WB + e) * N + ybase;
        u64* pb = pa + 512;
        *reinterpret_cast<ulonglong2*>(pa)     = make_ulonglong2(va[0], va[1]);
        *reinterpret_cast<ulonglong2*>(pa + 2) = make_ulonglong2(va[2], va[3]);
        *reinterpret_cast<ulonglong2*>(pb)     = make_ulonglong2(vb[0], vb[1]);
        *reinterpret_cast<ulonglong2*>(pb + 2) = make_ulonglong2(vb[2], vb[3]);
    }
}

// One FFT = one kept column kx. 2 columns per 128-thread block.
// The magnitude array m ALIASES the exchange buffer s (results are in
// registers after ph3), cutting smem/block ~8KB -> higher occupancy.
__global__ void __launch_bounds__(128) k_colfft(void) {
    __shared__ u64 s[2][S_SZ];
    __shared__ u64 tw[TW_SZ];
    __shared__ float red[8];            // 4 warps: min[0..3], max[4..7]
    int T = threadIdx.x, f = T >> 6, L = T & 63;
    #pragma unroll
    for (int j = T; j < 256; j += 128) tw[j + (j >> 4)] = g_tw[j];
    int bx  = blockIdx.x;               // img*257 + cg
    int img = bx / 257;
    int cg  = bx - img * 257;
    int kx  = 2*cg + f;                 // 0..513 (513 is padding)
    bool valid = (kx < W);
    __syncthreads();                    // tw ready

    const u64* cp = g_B + ((size_t)img * WB + kx) * N;
    // relabeled: contiguous 256B/warp loads
    u64 x[16];
    #pragma unroll
    for (int j = 0; j < 16; ++j)
        x[j] = cp[L + 64*((j >> 2) & 3) + 256*(j & 3)];
    fft_ph1(x, s[f], rev4_6(L));
    __syncthreads();
    fft_ph2(s[f], tw, L);
    __syncthreads();
    fft_ph3(s[f], tw, L, x);
    __syncthreads();                    // all ph3 reads of s done: safe to alias

    // log-magnitude straight from registers; fftshift along ky.
    // m overlays s[f] (4096B of 8736B available).
    float* m = reinterpret_cast<float*>(s[f]);
    float mn = 3.4e38f, mx = 0.0f;
    int mbase = 4*L;
    #pragma unroll
    for (int k = 0; k < 4; ++k)
        #pragma unroll
        for (int q = 0; q < 4; ++q) {
            int cshift = (256*q + 512) & (N - 1);   // literal per q: 512,768,0,256
            float vx, vy; upk(x[k + 4*q], vx, vy);
            float mag = log1pf(sqrtf(vx*vx + vy*vy));
            m[mbase + k + cshift] = mag;
            mn = fminf(mn, mag); mx = fmaxf(mx, mag);
        }
    #pragma unroll
    for (int o = 16; o; o >>= 1) {
        mn = fminf(mn, __shfl_xor_sync(0xffffffffu, mn, o));
        mx = fmaxf(mx, __shfl_xor_sync(0xffffffffu, mx, o));
    }
    int wid = T >> 5;
    if ((T & 31) == 0) { red[wid] = mn; red[4 + wid] = mx; }
    __syncthreads();                    // red + m[] ready
    if (L == 0 && valid) {
        float a  = fminf(red[2*f], red[2*f + 1]);
        float c2 = fmaxf(red[4 + 2*f], red[4 + 2*f + 1]);
        int b = img / 3;
        atomicMin(&g_mn[b], __float_as_uint(a));
        atomicMax(&g_mx[b], __float_as_uint(c2));
    }

    // antialiased triangle resize along kys (ramp weights), column + mirror
    if (valid) {
        int kxs1 = (kx + 512) & (N - 1);
        int kxs2 = 512 - kx;
        float* gt1 = g_T + ((size_t)img * N + kxs1) * OUT_HW;
        float* gt2 = g_T + ((size_t)img * N + kxs2) * OUT_HW;
        for (int oy = L; oy < OUT_HW; oy += 64) {
            float sf = ((float)oy + 0.5f) * (1024.0f/224.0f) - 0.5f;
            int i0 = max(0, (int)ceilf(sf - KRAD));
            int i1 = min(N - 1, (int)floorf(sf + KRAD));
            int ip = (int)floorf(sf);
            float acc1 = 0.0f, acc2 = 0.0f, sw = 0.0f;
            float w = 1.0f - (sf - (float)i0) * KSCL;
            int i = i0;
            for (; i <= ip; ++i) {
                acc1 += w * m[i];
                acc2 += w * m[(N - i) & (N - 1)];
                sw += w; w += KSCL;
            }
            w = 1.0f - ((float)i - sf) * KSCL;
            for (; i <= i1; ++i) {
                acc1 += w * m[i];
                acc2 += w * m[(N - i) & (N - 1)];
                sw += w; w -= KSCL;
            }
            float inv = 1.0f / sw;
            gt1[oy] = acc1 * inv;
            gt2[oy] = acc2 * inv;
        }
    }
}

__global__ void __launch_bounds__(224) k_resize2(float* __restrict__ out) {
    int blk = blockIdx.x;               // img*224 + ox
    int img = blk / OUT_HW;
    int ox  = blk - img * OUT_HW;
    int oy  = threadIdx.x;
    float sf = ((float)ox + 0.5f) * (1024.0f/224.0f) - 0.5f;
    int i0 = max(0, (int)ceilf(sf - KRAD));
    int i1 = min(N - 1, (int)floorf(sf + KRAD));
    int ip = (int)floorf(sf);
    float acc = 0.0f, sw = 0.0f;
    const float* base = g_T + (size_t)img * N * OUT_HW + oy;
    float w = 1.0f - (sf - (float)i0) * KSCL;
    int i = i0;
    for (; i <= ip; ++i) { acc += w * base[(size_t)i * OUT_HW]; sw += w; w += KSCL; }
    w = 1.0f - ((float)i - sf) * KSCL;
    for (; i <= i1; ++i) { acc += w * base[(size_t)i * OUT_HW]; sw += w; w -= KSCL; }
    int b = img / 3;
    float mn = __uint_as_float(g_mn[b]);
    float mx = __uint_as_float(g_mx[b]);
    float v = (acc / sw - mn) / (mx - mn + 1e-8f);
    out[((size_t)img * OUT_HW + oy) * OUT_HW + ox] = v;
}

extern "C" void kernel_launch(void* const* d_in, const int* in_sizes, int n_in,
                              void* d_out, int out_size) {
    (void)in_sizes; (void)n_in; (void)out_size;
    const float* in = (const float*)d_in[0];
    float* out = (float*)d_out;

    k_init<<<1, 256>>>();
    k_rowfft<<<NIMG * 128, 256>>>(in);
    k_colfft<<<NIMG * 257, 128>>>();
    k_resize2<<<NIMG * OUT_HW, 224>>>(out);
}